// round 14
// baseline (speedup 1.0000x reference)
#include <cuda_runtime.h>
#include <cuda_fp16.h>
#include <cstdint>
#include <cstddef>

#define Bn 256
#define Sn 128
#define En 1024

constexpr int MT   = 64;            // 4 subtiles of 16 rows per CTA
constexpr int NT   = 128;           // f-columns per chunk
constexpr int KT   = 128;           // K halfs per tile (256B rows)
constexpr int NFC  = En / NT;       // 8
constexpr int NKT  = En / KT;       // 8
constexpr int TILES = NFC * NKT;    // 64
constexpr int NTHR = 256;           // 8 warps: 2 (M) x 4 (N)
constexpr int WMN  = 2;
constexpr int WNN  = 4;

constexpr int A_TILE_B = MT * KT * 2;   // 16384
constexpr int B_TILE_B = NT * KT * 2;   // 32768
constexpr int STG_B    = A_TILE_B + B_TILE_B;     // 49152
constexpr int OFF_ITEM = 2 * STG_B;               // 98304 (16 ints: 2 passes x (4 src + 4 val))
constexpr int SMEM_TOTAL = OFF_ITEM + 64;         // 98368 -> 2 CTAs/SM
constexpr int OFF_SP   = 0;          // s_part / attn alias stage 0 (post-loop only)

constexpr int NCTA = 296;            // 2 x 148 SMs, exact residency
constexpr int ITEMS_PER_PASS = NCTA * 4;   // 1184
constexpr int MAX_ITEMS = 2368;      // 2 passes cover worst case T=1536
constexpr int W_F4 = En * En / 4;    // 262144 float4s of W

// fallback path constants
constexpr int GEMM_GRID = 384;
constexpr int XBLK  = 24;
constexpr int WCONV = 512;

// device-global scratch (allocations are forbidden)
__device__ __half g_Wh[En * En];
__device__ __half g_xh[Bn * Sn * En];
__device__ float  g_scp[MAX_ITEMS * 16];
__device__ int    g_itembase[Bn + 1];
__device__ int    g_item_src[MAX_ITEMS];
__device__ int    g_item_val[MAX_ITEMS];
__device__ int    gA1 = 0, gB1 = 0, gA2 = 0, gB2 = 0;   // barrier counters

// ---------------------------------------------------------------------------
__device__ __forceinline__ void cp16(uint32_t dst, const void* src, bool pred) {
    int sz = pred ? 16 : 0;
    asm volatile("cp.async.cg.shared.global [%0], [%1], 16, %2;\n"
                 :: "r"(dst), "l"(src), "r"(sz));
}
__device__ __forceinline__ void cp_commit() {
    asm volatile("cp.async.commit_group;\n");
}
__device__ __forceinline__ void cp_wait0() {
    asm volatile("cp.async.wait_group 0;\n");
}
__device__ __forceinline__ float tanha(float x) {
    float y;
    asm("tanh.approx.f32 %0, %1;" : "=f"(y) : "f"(x));
    return y;
}
__device__ __forceinline__ void ldsm4(uint32_t& r0, uint32_t& r1,
                                      uint32_t& r2, uint32_t& r3, uint32_t addr) {
    asm volatile("ldmatrix.sync.aligned.m8n8.x4.shared.b16 {%0,%1,%2,%3}, [%4];"
                 : "=r"(r0), "=r"(r1), "=r"(r2), "=r"(r3) : "r"(addr));
}
__device__ __forceinline__ void mma16816(float* c,
                                         uint32_t a0, uint32_t a1, uint32_t a2, uint32_t a3,
                                         uint32_t b0, uint32_t b1) {
    asm volatile(
        "mma.sync.aligned.m16n8k16.row.col.f32.f16.f16.f32 "
        "{%0,%1,%2,%3},{%4,%5,%6,%7},{%8,%9},{%0,%1,%2,%3};"
        : "+f"(c[0]), "+f"(c[1]), "+f"(c[2]), "+f"(c[3])
        : "r"(a0), "r"(a1), "r"(a2), "r"(a3), "r"(b0), "r"(b1));
}
__device__ __forceinline__ uint32_t cvt2u(float a, float b) {
    __half2 h = __floats2half2_rn(a, b);
    return *reinterpret_cast<uint32_t*>(&h);
}

// Grid barrier: exact-residency grid only. Counters self-reset for graph replay.
__device__ __forceinline__ void grid_barrier(int* cA, int* cB) {
    __syncthreads();
    if (threadIdx.x == 0) {
        __threadfence();
        atomicAdd(cA, 1);
        while (*((volatile int*)cA) < NCTA) { }
        __threadfence();
        int t = atomicAdd(cB, 1);
        if (t == NCTA - 1) { *cB = 0; *cA = 0; __threadfence(); }
    }
    __syncthreads();
}

// ---------------------------------------------------------------------------
// MEGA kernel: scan + convert + barrier + GEMM + barrier + finish.
// ---------------------------------------------------------------------------
extern __shared__ char smem[];

__global__ __launch_bounds__(NTHR, 2)
void mega_kernel(const float4* __restrict__ W4,
                 const float4* __restrict__ x4,
                 const float* __restrict__ u,
                 const int* __restrict__ doc,
                 float* __restrict__ out) {
    const int grp  = blockIdx.x;
    const int tid  = threadIdx.x;
    const int lane = tid & 31;
    const int wid  = tid >> 5;
    const int wm   = wid % WMN;
    const int wn   = wid / WMN;
    const int g    = lane >> 2;
    const int tg   = lane & 3;

    const uint32_t smem_u32 = (uint32_t)__cvta_generic_to_shared(smem);
    float* s_part = reinterpret_cast<float*>(smem + OFF_SP);
    int*   item_s = reinterpret_cast<int*>(smem + OFF_ITEM);

    // ---- 1. scan doc -> items + finish metadata ----
    int* docS = reinterpret_cast<int*>(smem);        // 256
    int* docL = docS + 256;                          // 256
    int* sc   = docS + 512;                          // 256 inclusive scan of nmt
    {
        int s0 = doc[2 * tid], e0 = doc[2 * tid + 1];
        docS[tid] = s0;
        docL[tid] = e0 - s0;
        sc[tid]   = (e0 - s0 + 15) >> 4;
    }
    __syncthreads();
    for (int off = 1; off < 256; off <<= 1) {
        int v = sc[tid];
        int add = (tid >= off) ? sc[tid - off] : 0;
        __syncthreads();
        sc[tid] = v + add;
        __syncthreads();
    }
    const int T = sc[255];
    const int passes = (T + ITEMS_PER_PASS - 1) / ITEMS_PER_PASS;   // 1 or 2

    int my_ib = 0, my_start = 0, my_len = 0;
    if (grp < Bn) {
        my_ib    = grp ? sc[grp - 1] : 0;
        my_start = docS[grp];
        my_len   = docL[grp];
    }
    if (tid < passes * 4) {
        int p = tid >> 2, j = tid & 3;
        int q = grp * 4 + p * ITEMS_PER_PASS + j;
        int src = 0, val = 0;
        if (q < T) {
            int lo = 0, hi = 255;
            while (lo < hi) { int mid = (lo + hi) >> 1; if (sc[mid] > q) hi = mid; else lo = mid + 1; }
            int b = lo;
            int st = q - (b ? sc[b - 1] : 0);
            src = b * Sn + docS[b] + st * 16;
            int v = docL[b] - st * 16;
            val = v > 16 ? 16 : v;
        }
        item_s[p * 8 + j]     = src;
        item_s[p * 8 + 4 + j] = val;
    }
    __syncthreads();

    // ---- 2. convert my items' x rows (disjoint across CTAs) ----
    for (int p = 0; p < passes; p++) {
        #pragma unroll
        for (int i = 0; i < 4; i++) {
            int src = item_s[p * 8 + i];
            int val = item_s[p * 8 + 4 + i];
            const float4* xr = x4 + (size_t)src * (En / 4);
            __half2* o = reinterpret_cast<__half2*>(g_xh);
            int r = 0;
            for (; r + 2 <= val; r += 2) {
                float4 v0 = xr[(size_t)r * (En / 4) + tid];
                float4 v1 = xr[(size_t)(r + 1) * (En / 4) + tid];
                size_t b0 = (size_t)(src + r) * (En / 2) + tid * 2;
                size_t b1 = (size_t)(src + r + 1) * (En / 2) + tid * 2;
                o[b0]     = __floats2half2_rn(v0.x, v0.y);
                o[b0 + 1] = __floats2half2_rn(v0.z, v0.w);
                o[b1]     = __floats2half2_rn(v1.x, v1.y);
                o[b1 + 1] = __floats2half2_rn(v1.z, v1.w);
            }
            if (r < val) {
                float4 v0 = xr[(size_t)r * (En / 4) + tid];
                size_t b0 = (size_t)(src + r) * (En / 2) + tid * 2;
                o[b0]     = __floats2half2_rn(v0.x, v0.y);
                o[b0 + 1] = __floats2half2_rn(v0.z, v0.w);
            }
        }
    }

    // ---- 3. convert my W slice ----
    {
        __half2* o = reinterpret_cast<__half2*>(g_Wh);
        for (int idx = grp * NTHR + tid; idx < W_F4; idx += NCTA * NTHR) {
            float4 v = W4[idx];
            o[idx * 2]     = __floats2half2_rn(v.x, v.y);
            o[idx * 2 + 1] = __floats2half2_rn(v.z, v.w);
        }
    }

    // ---- 4. grid barrier: W (and all x) fully converted ----
    grid_barrier(&gA1, &gB1);

    // ---- 5. GEMM passes ----
    const int fa_m = tid >> 4;
    const int fa_c = tid & 15;
    const int swz  = (fa_c ^ (fa_m & 7)) << 4;
    const int a_row   = (lane & 15);
    const int a_choff = (lane >> 4);
    const int b_rowin = (lane & 7) + ((lane >> 4) << 3);
    const int b_choff = ((lane >> 3) & 1);

    for (int p = 0; p < passes; p++) {
        const __half* arow[4];
        bool apred[4];
        #pragma unroll
        for (int i = 0; i < 4; i++) {
            arow[i]  = g_xh + (size_t)(item_s[p * 8 + i] + fa_m) * En + fa_c * 8;
            apred[i] = fa_m < item_s[p * 8 + 4 + i];
        }

        auto fill_full = [&](int t) {
            const int fc = t >> 3;
            const int k0 = (t & 7) * KT;
            const uint32_t aBase = smem_u32 + (t & 1) * STG_B;
            const uint32_t bBase = aBase + A_TILE_B;
            #pragma unroll
            for (int i = 0; i < 4; i++) {
                int m = fa_m + i * 16;
                cp16(aBase + m * 256 + swz, arow[i] + k0, apred[i]);
            }
            #pragma unroll
            for (int i = 0; i < 8; i++) {
                int n = fa_m + i * 16;
                cp16(bBase + n * 256 + swz,
                     g_Wh + (size_t)(fc * NT + n) * En + k0 + fa_c * 8, true);
            }
            cp_commit();
        };

        float acc[2][4][4];
        #pragma unroll
        for (int ms = 0; ms < 2; ms++)
            #pragma unroll
            for (int j = 0; j < 4; j++)
                #pragma unroll
                for (int i = 0; i < 4; i++) acc[ms][j][i] = 0.0f;
        float sacc[2][2] = {{0.f,0.f},{0.f,0.f}};

        fill_full(0);

        for (int fc = 0; fc < NFC; fc++) {
            for (int k = 0; k < NKT; k++) {
                const int t = fc * NKT + k;
                cp_wait0();
                __syncthreads();

                const uint32_t aBase = smem_u32 + (t & 1) * STG_B;
                const uint32_t bBase = aBase + A_TILE_B;

                const bool have_next = (t + 1 < TILES);
                const int  nfc = (t + 1) >> 3;
                const int  nk0 = ((t + 1) & 7) * KT;
                const uint32_t naBase = smem_u32 + ((t + 1) & 1) * STG_B;
                const uint32_t nbBase = naBase + A_TILE_B;

                #pragma unroll
                for (int ks = 0; ks < 8; ks++) {
                    if (have_next) {
                        if (ks < 4) {
                            int m = fa_m + ks * 16;
                            cp16(naBase + m * 256 + swz, arow[ks] + nk0, apred[ks]);
                        }
                        {
                            int n = fa_m + ks * 16;
                            cp16(nbBase + n * 256 + swz,
                                 g_Wh + (size_t)(nfc * NT + n) * En + nk0 + fa_c * 8, true);
                        }
                    }
                    uint32_t af[2][4];
                    #pragma unroll
                    for (int ms = 0; ms < 2; ms++) {
                        int row = (wm * 2 + ms) * 16 + a_row;
                        int chv = 2 * ks + a_choff;
                        uint32_t addr = aBase + row * 256 + ((chv ^ (row & 7)) << 4);
                        ldsm4(af[ms][0], af[ms][1], af[ms][2], af[ms][3], addr);
                    }
                    uint32_t bf[2][4];
                    #pragma unroll
                    for (int jp = 0; jp < 2; jp++) {
                        int nrow = wn * 32 + jp * 16 + b_rowin;
                        int chv = 2 * ks + b_choff;
                        uint32_t addr = bBase + nrow * 256 + ((chv ^ (nrow & 7)) << 4);
                        ldsm4(bf[jp][0], bf[jp][1], bf[jp][2], bf[jp][3], addr);
                    }
                    #pragma unroll
                    for (int ms = 0; ms < 2; ms++) {
                        #pragma unroll
                        for (int j = 0; j < 4; j++) {
                            mma16816(acc[ms][j],
                                     af[ms][0], af[ms][1], af[ms][2], af[ms][3],
                                     bf[j >> 1][(j & 1) * 2], bf[j >> 1][(j & 1) * 2 + 1]);
                        }
                    }
                }
                cp_commit();
            }

            #pragma unroll
            for (int ms = 0; ms < 2; ms++) {
                #pragma unroll
                for (int j = 0; j < 4; j++) {
                    int f = fc * NT + wn * 32 + j * 8 + 2 * tg;
                    float u0 = __ldg(u + f), u1 = __ldg(u + f + 1);
                    sacc[ms][0] += tanha(acc[ms][j][0]) * u0 + tanha(acc[ms][j][1]) * u1;
                    sacc[ms][1] += tanha(acc[ms][j][2]) * u0 + tanha(acc[ms][j][3]) * u1;
                    acc[ms][j][0] = 0.f; acc[ms][j][1] = 0.f;
                    acc[ms][j][2] = 0.f; acc[ms][j][3] = 0.f;
                }
            }
        }

        // reduction -> s_part (stage 0 free: last tile read stage 1)
        #pragma unroll
        for (int ms = 0; ms < 2; ms++) {
            #pragma unroll
            for (int rg = 0; rg < 2; rg++) {
                float v = sacc[ms][rg];
                v += __shfl_xor_sync(0xffffffffu, v, 1);
                v += __shfl_xor_sync(0xffffffffu, v, 2);
                if (tg == 0) {
                    int row = (wm * 2 + ms) * 16 + rg * 8 + g;
                    s_part[row * WNN + wn] = v;
                }
            }
        }
        __syncthreads();

        if (wid == 0) {
            int qb16 = (grp * 4 + p * ITEMS_PER_PASS) * 16;
            #pragma unroll
            for (int i = 0; i < 2; i++) {
                int r = lane + 32 * i;
                float sv = s_part[r * WNN + 0] + s_part[r * WNN + 1] +
                           s_part[r * WNN + 2] + s_part[r * WNN + 3];
                g_scp[qb16 + r] = sv;
            }
        }
        __syncthreads();   // protect s_part before next pass's fills
    }

    // ---- 6. grid barrier: all scores visible ----
    grid_barrier(&gA2, &gB2);

    // ---- 7. finish phase: CTAs 0..255 ----
    if (grp < Bn) {
        const int b     = grp;
        const int start = my_start;
        const int len   = my_len;
        const int ib    = my_ib;
        float* attn_s = reinterpret_cast<float*>(smem);   // stage 0, free now

        if (wid == 0) {
            float v[3];
            #pragma unroll
            for (int i = 0; i < 3; i++) {
                int r = lane + 32 * i;
                v[i] = (r < len)
                     ? g_scp[(ib + (r >> 4)) * 16 + (r & 15)]
                     : -3.0e38f;
            }
            float mx = fmaxf(v[0], fmaxf(v[1], v[2]));
            #pragma unroll
            for (int o = 16; o > 0; o >>= 1)
                mx = fmaxf(mx, __shfl_xor_sync(0xffffffffu, mx, o));
            float e[3];
            float ssum = 0.0f;
            #pragma unroll
            for (int i = 0; i < 3; i++) {
                int r = lane + 32 * i;
                e[i] = (r < len) ? __expf(v[i] - mx) : 0.0f;
                ssum += e[i];
            }
            #pragma unroll
            for (int o = 16; o > 0; o >>= 1)
                ssum += __shfl_xor_sync(0xffffffffu, ssum, o);
            float inv = 1.0f / ssum;
            #pragma unroll
            for (int i = 0; i < 3; i++) {
                int r = lane + 32 * i;
                attn_s[r] = (r < len) ? e[i] * inv : 0.0f;
            }
        }
        __syncthreads();

        // GEMV from fp16 x, 4-way unrolled
        {
            const uint2* xb = reinterpret_cast<const uint2*>(
                g_xh + (size_t)(b * Sn + start) * En);
            float4 a0 = make_float4(0.f, 0.f, 0.f, 0.f);
            float4 a1 = make_float4(0.f, 0.f, 0.f, 0.f);
            float4 a2 = make_float4(0.f, 0.f, 0.f, 0.f);
            float4 a3 = make_float4(0.f, 0.f, 0.f, 0.f);
            int s = 0;
            for (; s + 4 <= len; s += 4) {
                float w0 = attn_s[s],     w1 = attn_s[s + 1];
                float w2 = attn_s[s + 2], w3 = attn_s[s + 3];
                uint2 v0 = xb[(size_t)s * (En / 4) + tid];
                uint2 v1 = xb[(size_t)(s + 1) * (En / 4) + tid];
                uint2 v2 = xb[(size_t)(s + 2) * (En / 4) + tid];
                uint2 v3 = xb[(size_t)(s + 3) * (En / 4) + tid];
                float2 p0 = __half22float2(*reinterpret_cast<__half2*>(&v0.x));
                float2 p1 = __half22float2(*reinterpret_cast<__half2*>(&v0.y));
                float2 q0 = __half22float2(*reinterpret_cast<__half2*>(&v1.x));
                float2 q1 = __half22float2(*reinterpret_cast<__half2*>(&v1.y));
                float2 r0 = __half22float2(*reinterpret_cast<__half2*>(&v2.x));
                float2 r1 = __half22float2(*reinterpret_cast<__half2*>(&v2.y));
                float2 s0 = __half22float2(*reinterpret_cast<__half2*>(&v3.x));
                float2 s1 = __half22float2(*reinterpret_cast<__half2*>(&v3.y));
                a0.x += w0 * p0.x; a0.y += w0 * p0.y; a0.z += w0 * p1.x; a0.w += w0 * p1.y;
                a1.x += w1 * q0.x; a1.y += w1 * q0.y; a1.z += w1 * q1.x; a1.w += w1 * q1.y;
                a2.x += w2 * r0.x; a2.y += w2 * r0.y; a2.z += w2 * r1.x; a2.w += w2 * r1.y;
                a3.x += w3 * s0.x; a3.y += w3 * s0.y; a3.z += w3 * s1.x; a3.w += w3 * s1.y;
            }
            for (; s < len; s++) {
                float w0 = attn_s[s];
                uint2 v0 = xb[(size_t)s * (En / 4) + tid];
                float2 p0 = __half22float2(*reinterpret_cast<__half2*>(&v0.x));
                float2 p1 = __half22float2(*reinterpret_cast<__half2*>(&v0.y));
                a0.x += w0 * p0.x; a0.y += w0 * p0.y; a0.z += w0 * p1.x; a0.w += w0 * p1.y;
            }
            a0.x += a1.x + a2.x + a3.x;
            a0.y += a1.y + a2.y + a3.y;
            a0.z += a1.z + a2.z + a3.z;
            a0.w += a1.w + a2.w + a3.w;
            reinterpret_cast<float4*>(out)[(size_t)b * (En / 4) + tid] = a0;
        }

        if (b == Bn - 1 && tid < Sn) {
            int r = tid - start;
            out[(size_t)Bn * En + tid] = (r >= 0 && r < len) ? attn_s[r] : 0.0f;
        }
    }
}

// ===========================================================================
// FALLBACK path (R13): conv + gemm + finish, no grid barriers.
// ===========================================================================
__global__ __launch_bounds__(256)
void conv_kernel(const float4* __restrict__ W4,
                 const float4* __restrict__ x4,
                 const int* __restrict__ doc) {
    const int bx = blockIdx.x;
    const int t  = threadIdx.x;
    if (bx < WCONV) {
        __half2* o = reinterpret_cast<__half2*>(g_Wh);
        #pragma unroll
        for (int i = 0; i < 2; i++) {
            int idx = (bx * 2 + i) * 256 + t;
            float4 v = W4[idx];
            o[idx * 2]     = __floats2half2_rn(v.x, v.y);
            o[idx * 2 + 1] = __floats2half2_rn(v.z, v.w);
        }
    } else if (bx < WCONV + Bn * XBLK) {
        const int b  = (bx - WCONV) / XBLK;
        const int gq = (bx - WCONV) % XBLK;
        const int start = doc[2 * b];
        const int end   = doc[2 * b + 1];
        __half2* o = reinterpret_cast<__half2*>(g_xh);
        #pragma unroll
        for (int i = 0; i < 4; i++) {
            int s = start + gq * 4 + i;
            if (s < end) {
                size_t base = (size_t)(b * Sn + s) * (En / 4) + t;
                float4 v = x4[base];
                o[base * 2]     = __floats2half2_rn(v.x, v.y);
                o[base * 2 + 1] = __floats2half2_rn(v.z, v.w);
            }
        }
    } else {
        __shared__ int nmt_s[Bn];
        const int b = t;
        const int start = doc[2 * b];
        const int len   = doc[2 * b + 1] - start;
        const int nmt   = (len + 15) >> 4;
        nmt_s[b] = nmt;
        __syncthreads();
        if (t == 0) {
            int acc = 0;
            for (int i = 0; i < Bn; i++) { g_itembase[i] = acc; acc += nmt_s[i]; }
            g_itembase[Bn] = acc;
        }
        __syncthreads();
        const int base = g_itembase[b];
        for (int st = 0; st < nmt; st++) {
            int v = len - st * 16; if (v > 16) v = 16;
            g_item_src[base + st] = b * Sn + start + st * 16;
            g_item_val[base + st] = v;
        }
        __syncthreads();
        const int T = g_itembase[Bn];
        for (int i = T + t; i < MAX_ITEMS; i += 256) {
            g_item_src[i] = 0;
            g_item_val[i] = 0;
        }
    }
}

__global__ __launch_bounds__(NTHR, 2)
void gemm_kernel(const float* __restrict__ u) {
    const int grp = blockIdx.x;
    const int tid  = threadIdx.x;
    const int lane = tid & 31;
    const int wid  = tid >> 5;
    const int wm   = wid % WMN;
    const int wn   = wid / WMN;
    const int g    = lane >> 2;
    const int tg   = lane & 3;

    const uint32_t smem_u32 = (uint32_t)__cvta_generic_to_shared(smem);
    float* s_part = reinterpret_cast<float*>(smem + OFF_SP);
    int*   item_s = reinterpret_cast<int*>(smem + OFF_ITEM);

    if (tid < 4) {
        item_s[tid]     = g_item_src[grp * 4 + tid];
        item_s[4 + tid] = g_item_val[grp * 4 + tid];
    }
    __syncthreads();

    const int fa_m = tid >> 4;
    const int fa_c = tid & 15;
    const int swz  = (fa_c ^ (fa_m & 7)) << 4;

    const __half* arow[4];
    bool apred[4];
    #pragma unroll
    for (int i = 0; i < 4; i++) {
        arow[i]  = g_xh + (size_t)(item_s[i] + fa_m) * En + fa_c * 8;
        apred[i] = fa_m < item_s[4 + i];
    }

    auto fill_full = [&](int t) {
        const int fc = t >> 3;
        const int k0 = (t & 7) * KT;
        const uint32_t aBase = smem_u32 + (t & 1) * STG_B;
        const uint32_t bBase = aBase + A_TILE_B;
        #pragma unroll
        for (int i = 0; i < 4; i++) {
            int m = fa_m + i * 16;
            cp16(aBase + m * 256 + swz, arow[i] + k0, apred[i]);
        }
        #pragma unroll
        for (int i = 0; i < 8; i++) {
            int n = fa_m + i * 16;
            cp16(bBase + n * 256 + swz,
                 g_Wh + (size_t)(fc * NT + n) * En + k0 + fa_c * 8, true);
        }
        cp_commit();
    };

    float acc[2][4][4];
    #pragma unroll
    for (int ms = 0; ms < 2; ms++)
        #pragma unroll
        for (int j = 0; j < 4; j++)
            #pragma unroll
            for (int i = 0; i < 4; i++) acc[ms][j][i] = 0.0f;
    float sacc[2][2] = {{0.f,0.f},{0.f,0.f}};

    const int a_row   = (lane & 15);
    const int a_choff = (lane >> 4);
    const int b_rowin = (lane & 7) + ((lane >> 4) << 3);
    const int b_choff = ((lane >> 3) & 1);

    fill_full(0);

    for (int fc = 0; fc < NFC; fc++) {
        for (int k = 0; k < NKT; k++) {
            const int t = fc * NKT + k;
            cp_wait0();
            __syncthreads();

            const uint32_t aBase = smem_u32 + (t & 1) * STG_B;
            const uint32_t bBase = aBase + A_TILE_B;

            const bool have_next = (t + 1 < TILES);
            const int  nfc = (t + 1) >> 3;
            const int  nk0 = ((t + 1) & 7) * KT;
            const uint32_t naBase = smem_u32 + ((t + 1) & 1) * STG_B;
            const uint32_t nbBase = naBase + A_TILE_B;

            #pragma unroll
            for (int ks = 0; ks < 8; ks++) {
                if (have_next) {
                    if (ks < 4) {
                        int m = fa_m + ks * 16;
                        cp16(naBase + m * 256 + swz, arow[ks] + nk0, apred[ks]);
                    }
                    {
                        int n = fa_m + ks * 16;
                        cp16(nbBase + n * 256 + swz,
                             g_Wh + (size_t)(nfc * NT + n) * En + nk0 + fa_c * 8, true);
                    }
                }
                uint32_t af[2][4];
                #pragma unroll
                for (int ms = 0; ms < 2; ms++) {
                    int row = (wm * 2 + ms) * 16 + a_row;
                    int chv = 2 * ks + a_choff;
                    uint32_t addr = aBase + row * 256 + ((chv ^ (row & 7)) << 4);
                    ldsm4(af[ms][0], af[ms][1], af[ms][2], af[ms][3], addr);
                }
                uint32_t bf[2][4];
                #pragma unroll
                for (int jp = 0; jp < 2; jp++) {
                    int nrow = wn * 32 + jp * 16 + b_rowin;
                    int chv = 2 * ks + b_choff;
                    uint32_t addr = bBase + nrow * 256 + ((chv ^ (nrow & 7)) << 4);
                    ldsm4(bf[jp][0], bf[jp][1], bf[jp][2], bf[jp][3], addr);
                }
                #pragma unroll
                for (int ms = 0; ms < 2; ms++) {
                    #pragma unroll
                    for (int j = 0; j < 4; j++) {
                        mma16816(acc[ms][j],
                                 af[ms][0], af[ms][1], af[ms][2], af[ms][3],
                                 bf[j >> 1][(j & 1) * 2], bf[j >> 1][(j & 1) * 2 + 1]);
                    }
                }
            }
            cp_commit();
        }

        #pragma unroll
        for (int ms = 0; ms < 2; ms++) {
            #pragma unroll
            for (int j = 0; j < 4; j++) {
                int f = fc * NT + wn * 32 + j * 8 + 2 * tg;
                float u0 = __ldg(u + f), u1 = __ldg(u + f + 1);
                sacc[ms][0] += tanha(acc[ms][j][0]) * u0 + tanha(acc[ms][j][1]) * u1;
                sacc[ms][1] += tanha(acc[ms][j][2]) * u0 + tanha(acc[ms][j][3]) * u1;
                acc[ms][j][0] = 0.f; acc[ms][j][1] = 0.f;
                acc[ms][j][2] = 0.f; acc[ms][j][3] = 0.f;
            }
        }
    }

    #pragma unroll
    for (int ms = 0; ms < 2; ms++) {
        #pragma unroll
        for (int rg = 0; rg < 2; rg++) {
            float v = sacc[ms][rg];
            v += __shfl_xor_sync(0xffffffffu, v, 1);
            v += __shfl_xor_sync(0xffffffffu, v, 2);
            if (tg == 0) {
                int row = (wm * 2 + ms) * 16 + rg * 8 + g;
                s_part[row * WNN + wn] = v;
            }
        }
    }
    __syncthreads();

    if (wid == 0) {
        #pragma unroll
        for (int i = 0; i < 2; i++) {
            int r = lane + 32 * i;
            float sv = s_part[r * WNN + 0] + s_part[r * WNN + 1] +
                       s_part[r * WNN + 2] + s_part[r * WNN + 3];
            g_scp[grp * MT + r] = sv;
        }
    }
}

__global__ __launch_bounds__(256)
void finish_kernel(const int* __restrict__ doc, float* __restrict__ out) {
    const int b    = blockIdx.x;
    const int tid  = threadIdx.x;
    const int lane = tid & 31;
    const int wid  = tid >> 5;

    __shared__ float attn_s[96];

    const int start = doc[2 * b];
    const int len   = doc[2 * b + 1] - start;
    const int ib    = g_itembase[b];

    if (wid == 0) {
        float v[3];
        #pragma unroll
        for (int i = 0; i < 3; i++) {
            int r = lane + 32 * i;
            v[i] = (r < len) ? g_scp[(ib + (r >> 4)) * 16 + (r & 15)] : -3.0e38f;
        }
        float mx = fmaxf(v[0], fmaxf(v[1], v[2]));
        #pragma unroll
        for (int o = 16; o > 0; o >>= 1)
            mx = fmaxf(mx, __shfl_xor_sync(0xffffffffu, mx, o));
        float e[3];
        float ssum = 0.0f;
        #pragma unroll
        for (int i = 0; i < 3; i++) {
            int r = lane + 32 * i;
            e[i] = (r < len) ? __expf(v[i] - mx) : 0.0f;
            ssum += e[i];
        }
        #pragma unroll
        for (int o = 16; o > 0; o >>= 1)
            ssum += __shfl_xor_sync(0xffffffffu, ssum, o);
        float inv = 1.0f / ssum;
        #pragma unroll
        for (int i = 0; i < 3; i++) {
            int r = lane + 32 * i;
            attn_s[r] = (r < len) ? e[i] * inv : 0.0f;
        }
    }
    __syncthreads();

    {
        const uint2* xb = reinterpret_cast<const uint2*>(
            g_xh + (size_t)(b * Sn + start) * En);
        float4 a0 = make_float4(0.f, 0.f, 0.f, 0.f);
        float4 a1 = make_float4(0.f, 0.f, 0.f, 0.f);
        int s = 0;
        for (; s + 2 <= len; s += 2) {
            float w0 = attn_s[s], w1 = attn_s[s + 1];
            uint2 v0 = xb[(size_t)s * (En / 4) + tid];
            uint2 v1 = xb[(size_t)(s + 1) * (En / 4) + tid];
            float2 p0 = __half22float2(*reinterpret_cast<__half2*>(&v0.x));
            float2 p1 = __half22float2(*reinterpret_cast<__half2*>(&v0.y));
            float2 q0 = __half22float2(*reinterpret_cast<__half2*>(&v1.x));
            float2 q1 = __half22float2(*reinterpret_cast<__half2*>(&v1.y));
            a0.x += w0 * p0.x; a0.y += w0 * p0.y; a0.z += w0 * p1.x; a0.w += w0 * p1.y;
            a1.x += w1 * q0.x; a1.y += w1 * q0.y; a1.z += w1 * q1.x; a1.w += w1 * q1.y;
        }
        if (s < len) {
            float w0 = attn_s[s];
            uint2 v0 = xb[(size_t)s * (En / 4) + tid];
            float2 p0 = __half22float2(*reinterpret_cast<__half2*>(&v0.x));
            float2 p1 = __half22float2(*reinterpret_cast<__half2*>(&v0.y));
            a0.x += w0 * p0.x; a0.y += w0 * p0.y; a0.z += w0 * p1.x; a0.w += w0 * p1.y;
        }
        a0.x += a1.x; a0.y += a1.y; a0.z += a1.z; a0.w += a1.w;
        reinterpret_cast<float4*>(out)[(size_t)b * (En / 4) + tid] = a0;
    }

    if (b == Bn - 1 && tid < Sn) {
        int r = tid - start;
        out[(size_t)Bn * En + tid] = (r >= 0 && r < len) ? attn_s[r] : 0.0f;
    }
}

// ---------------------------------------------------------------------------
extern "C" void kernel_launch(void* const* d_in, const int* in_sizes, int n_in,
                              void* d_out, int out_size) {
    const float* x   = (const float*)d_in[0];
    const float* W   = (const float*)d_in[1];
    const float* u   = (const float*)d_in[2];
    const int*   doc = (const int*)d_in[3];
    float* out = (float*)d_out;

    static int mode = -1;   // decided once; same decision every call (deterministic)
    if (mode < 0) {
        cudaFuncSetAttribute(mega_kernel,
                             cudaFuncAttributeMaxDynamicSharedMemorySize, SMEM_TOTAL);
        cudaFuncSetAttribute(gemm_kernel,
                             cudaFuncAttributeMaxDynamicSharedMemorySize, SMEM_TOTAL);
        int dev = 0, nsm = 0, occ = 0;
        cudaGetDevice(&dev);
        cudaDeviceGetAttribute(&nsm, cudaDevAttrMultiProcessorCount, dev);
        cudaOccupancyMaxActiveBlocksPerMultiprocessor(&occ, mega_kernel, NTHR, SMEM_TOTAL);
        mode = (occ >= 2 && nsm * 2 >= NCTA) ? 1 : 0;
    }

    if (mode == 1) {
        mega_kernel<<<NCTA, NTHR, SMEM_TOTAL>>>(
            (const float4*)W, (const float4*)x, u, doc, out);
    } else {
        conv_kernel<<<WCONV + Bn * XBLK + 1, 256>>>(
            (const float4*)W, (const float4*)x, doc);
        gemm_kernel<<<GEMM_GRID, NTHR, SMEM_TOTAL>>>(u);
        finish_kernel<<<Bn, 256>>>(doc, out);
    }
}